// round 15
// baseline (speedup 1.0000x reference)
#include <cuda_runtime.h>
#include <cuda_fp16.h>
#include <cstdint>

#define D_IN   1024
#define D_OUTD 1024
#define NTREES 12
#define NINT   7
#define NCOL   96      // 84 decision cols + 12 gate cols; also 12 trees * 8 leaves
#define NHEADS 3
#define MAX_TOK 8192

// scratch
__device__ __half   g_coefh[MAX_TOK * NCOL];        // [tok][j]  (k2 A operand, fp16)
__device__ __half   g_loth[NHEADS * D_OUTD * NCOL]; // [h][d][j] (k2 B operand, fp16)
__device__ uint32_t g_whu[NCOL * (D_IN / 2)];       // fp16x2 weights [96][1024]

__device__ __forceinline__ uint32_t smem_u32(const void* p) {
    uint32_t a;
    asm("{ .reg .u64 t; cvta.to.shared.u64 t, %1; cvt.u32.u64 %0, t; }" : "=r"(a) : "l"(p));
    return a;
}
__device__ __forceinline__ void cpasync16(uint32_t dst, const void* src) {
    asm volatile("cp.async.cg.shared.global [%0], [%1], 16;" :: "r"(dst), "l"(src) : "memory");
}

#define MMA_F16(acc, a, b)                                                      \
    asm("mma.sync.aligned.m16n8k16.row.col.f32.f16.f16.f32 "                    \
        "{%0,%1,%2,%3}, {%4,%5,%6,%7}, {%8,%9}, {%0,%1,%2,%3};"                 \
        : "+f"((acc)[0]), "+f"((acc)[1]), "+f"((acc)[2]), "+f"((acc)[3])        \
        : "r"((a)[0]), "r"((a)[1]), "r"((a)[2]), "r"((a)[3]),                   \
          "r"((b)[0]), "r"((b)[1]))

#define LDMX4(r0, r1, r2, r3, addr)                                             \
    asm volatile("ldmatrix.sync.aligned.m8n8.x4.shared.b16 {%0,%1,%2,%3}, [%4];"\
        : "=r"(r0), "=r"(r1), "=r"(r2), "=r"(r3) : "r"(addr))

#define LDMX2(r0, r1, addr)                                                     \
    asm volatile("ldmatrix.sync.aligned.m8n8.x2.shared.b16 {%0,%1}, [%2];"      \
        : "=r"(r0), "=r"(r1) : "r"(addr))

// ---------------------------------------------------------------------------
// Prep kernel: blocks 0..95 convert weights to fp16;
//              blocks 96..383 transpose LO -> fp16 [h][d][j]   (R14 verbatim)
// ---------------------------------------------------------------------------
__global__ void k_prep(const float* __restrict__ dw, const float* __restrict__ gw,
                       const float* __restrict__ lo)
{
    const int b = blockIdx.x;
    if (b < NCOL) {
        const int row = b;
        const float* src = (row < 84) ? (dw + (size_t)row * D_IN)
                                      : (gw + (size_t)(row - 84) * D_IN);
        for (int k = threadIdx.x * 4; k < D_IN; k += blockDim.x * 4) {
            float4 v = *(const float4*)&src[k];
            __half2 h0 = __floats2half2_rn(v.x, v.y);
            __half2 h1 = __floats2half2_rn(v.z, v.w);
            uint32_t o = (uint32_t)(row * D_IN + k) >> 1;
            g_whu[o] = *(uint32_t*)&h0;
            g_whu[o + 1] = *(uint32_t*)&h1;
        }
    } else {
        __shared__ float t[32][33];
        const int tt = b - NCOL;                    // 0..287
        const int d0 = (tt & 31) * 32;
        const int j0 = ((tt >> 5) % 3) * 32;
        const int h  = tt / 96;
        const int tx = threadIdx.x & 31, ty = threadIdx.x >> 5;  // 32 x 8
#pragma unroll
        for (int i = 0; i < 32; i += 8)
            t[ty + i][tx] = lo[((size_t)h * NCOL + (j0 + ty + i)) * D_OUTD + d0 + tx];
        __syncthreads();
#pragma unroll
        for (int i = 0; i < 32; i += 8)
            g_loth[((size_t)h * D_OUTD + (d0 + ty + i)) * NCOL + j0 + tx] =
                __float2half_rn(t[tx][ty + i]);
    }
}

// ---------------------------------------------------------------------------
// Kernel 1: routing GEMM, single fp16 operands.
//   CTA tile 32 tok x 96 col, grid = ntok/32 = 256 CTAs, 256 threads
//   (8 warps: 2m x 4n, warp tile 16x24), KC=64, 3-STAGE cp.async ring,
//   single pipeline sync + one convert sync per chunk.  2 CTAs/SM.
// smem bytes: stage s at s*23040 { x raw 32x72 f32 [0,9216),
//   w fp16 96x144B [9216,23040) }; Xh plane @69120 (32x144B = 4608);
//   consts @73728 (768B).  Ds epilogue overlay @0 (32x100 f32).
// ---------------------------------------------------------------------------
#define T1     256
#define KC1    64
#define STG1B  23040
#define XH_B   69120u
#define CST_F  18432
#define SMEM1  (73728 + 768)

__device__ __forceinline__ void k1_stage(uint32_t base, const float* x, int tokbase,
                                          int kb, int tid)
{
#pragma unroll
    for (int i = 0; i < 2; i++) {                 // x raw: 32 rows x 16 float4
        int idx = i * T1 + tid;
        int row = idx >> 4, c4 = idx & 15;
        cpasync16(base + (uint32_t)(row * 72 + 4 * c4) * 4,
                  &x[(size_t)(tokbase + row) * D_IN + kb + 4 * c4]);
    }
#pragma unroll
    for (int i = 0; i < 3; i++) {                 // w fp16: 96 rows x 8 cp16
        int idx = i * T1 + tid;
        int row = idx >> 3, q = idx & 7;
        const char* src = (const char*)g_whu + (size_t)row * (D_IN * 2)
                        + kb * 2 + q * 16;
        cpasync16(base + 9216u + (uint32_t)(row * 144 + q * 16), src);
    }
}

__global__ __launch_bounds__(T1, 2) void k1_mma(
    const float* __restrict__ x,
    const float* __restrict__ db,
    const float* __restrict__ ntl,
    const float* __restrict__ gb,
    int ntok)
{
    extern __shared__ float sm[];
    const uint32_t sbase = smem_u32(sm);
    float* sInvT = sm + CST_F;
    float* sBias = sInvT + 84;
    float* sGb   = sBias + 84;

    const int tid = threadIdx.x;
    const int lane = tid & 31, wid = tid >> 5;
    const int m0 = (wid & 1) * 16;      // 2 m-warps x 16 rows
    const int n0 = (wid >> 1) * 24;     // 4 n-warps x 24 cols
    const int tokbase = blockIdx.x * 32;

    const int la_row = (lane & 7) + ((lane >> 3) & 1) * 8;
    const int la_col = (lane >> 4) * 8;
    const int lb_row = (lane & 7) + (lane >> 4) * 8;
    const int lb_col = ((lane >> 3) & 1) * 8;

    if (tid < 84) {
        float z = ntl[tid] + 0.5413f;
        float sp = (z > 15.f) ? z : log1pf(__expf(z));
        sInvT[tid] = 1.0f / sp;
        sBias[tid] = db[tid];
    } else if (tid >= 96 && tid < 96 + NTREES) {
        sGb[tid - 96] = gb[tid - 96];
    }

    float acc[3][4];
#pragma unroll
    for (int tn = 0; tn < 3; tn++)
#pragma unroll
        for (int q = 0; q < 4; q++) acc[tn][q] = 0.f;

    k1_stage(sbase, x, tokbase, 0, tid);
    asm volatile("cp.async.commit_group;" ::: "memory");
    k1_stage(sbase + STG1B, x, tokbase, KC1, tid);
    asm volatile("cp.async.commit_group;" ::: "memory");

    const int NCHUNK = D_IN / KC1;   // 16
    for (int ck = 0; ck < NCHUNK; ck++) {
        if (ck + 1 < NCHUNK) {
            asm volatile("cp.async.wait_group 1;" ::: "memory");
        } else {
            asm volatile("cp.async.wait_group 0;" ::: "memory");
        }
        __syncthreads();    // chunk ck staged; plane + slot (ck+2)%3 free
        if (ck + 2 < NCHUNK) {
            k1_stage(sbase + (uint32_t)((ck + 2) % 3) * STG1B, x, tokbase,
                     (ck + 2) * KC1, tid);
            asm volatile("cp.async.commit_group;" ::: "memory");
        }

        // ---- convert x chunk (32x64) to fp16 plane, once per element ----
        const float* Xs = sm + (uint32_t)(ck % 3) * (STG1B / 4);
#pragma unroll
        for (int i = 0; i < 2; i++) {
            int idx = i * T1 + tid;
            int row = idx >> 4, c4 = idx & 15;
            float4 v = *(const float4*)&Xs[row * 72 + 4 * c4];
            __half2 h0 = __floats2half2_rn(v.x, v.y);
            __half2 h1 = __floats2half2_rn(v.z, v.w);
            uint32_t off = (uint32_t)(row * 144 + 8 * c4);
            asm volatile("st.shared.v2.b32 [%0], {%1,%2};"
                         :: "r"(sbase + XH_B + off),
                            "r"(*(uint32_t*)&h0), "r"(*(uint32_t*)&h1));
        }
        __syncthreads();

        const uint32_t wb = sbase + (uint32_t)(ck % 3) * STG1B + 9216u;

#pragma unroll
        for (int ks = 0; ks < KC1 / 16; ks++) {
            const int kk = ks * 16;
            uint32_t ah[4], bh[3][2];
            {
                uint32_t ao = (uint32_t)((m0 + la_row) * 144 + (kk + la_col) * 2);
                LDMX4(ah[0], ah[1], ah[2], ah[3], sbase + XH_B + ao);
            }
#pragma unroll
            for (int tn = 0; tn < 3; tn++) {
                uint32_t bo = (uint32_t)((n0 + tn * 8 + lb_row) * 144 + (kk + lb_col) * 2);
                LDMX2(bh[tn][0], bh[tn][1], wb + bo);
            }
#pragma unroll
            for (int tn = 0; tn < 3; tn++)
                MMA_F16(acc[tn], ah, bh[tn]);
        }
    }

    // ---- logits to smem Ds[32][100], then scalar epilogue ----
    __syncthreads();
    float* Ds = sm;
    {
        const int r = lane >> 2, c = lane & 3;
#pragma unroll
        for (int tn = 0; tn < 3; tn++) {
            float* p = &Ds[(m0 + r) * 100 + n0 + tn * 8 + 2 * c];
            p[0] = acc[tn][0];
            p[1] = acc[tn][1];
            p[8 * 100] = acc[tn][2];
            p[8 * 100 + 1] = acc[tn][3];
        }
    }
    __syncthreads();

    if (tid < 32) {
        const float* d = &Ds[tid * 100];
        float g[NTREES];
        float m = -1e30f;
#pragma unroll
        for (int t = 0; t < NTREES; t++) { g[t] = d[84 + t] + sGb[t]; m = fmaxf(m, g[t]); }
        float s = 0.f;
#pragma unroll
        for (int t = 0; t < NTREES; t++) { g[t] = __expf(g[t] - m); s += g[t]; }
        float inv = 1.0f / s;

        const int tok = tokbase + tid;
        __half2* orow = (__half2*)&g_coefh[(size_t)tok * NCOL];
#pragma unroll
        for (int t = 0; t < NTREES; t++) {
            float w = g[t] * inv;
            float p[NINT];
#pragma unroll
            for (int n = 0; n < NINT; n++) {
                float z = (d[t * 7 + n] + sBias[t * 7 + n]) * sInvT[t * 7 + n];
                p[n] = 1.0f / (1.0f + __expf(-z));
            }
            float a0 = p[0], a1 = 1.f - p[0];
            orow[t * 4 + 0] = __floats2half2_rn(w * a0 * p[1] * p[3],
                                                w * a0 * p[1] * (1.f - p[3]));
            orow[t * 4 + 1] = __floats2half2_rn(w * a0 * (1.f - p[1]) * p[4],
                                                w * a0 * (1.f - p[1]) * (1.f - p[4]));
            orow[t * 4 + 2] = __floats2half2_rn(w * a1 * p[2] * p[5],
                                                w * a1 * p[2] * (1.f - p[5]));
            orow[t * 4 + 3] = __floats2half2_rn(w * a1 * (1.f - p[2]) * p[6],
                                                w * a1 * (1.f - p[2]) * (1.f - p[6]));
        }
    }
}

// ---------------------------------------------------------------------------
// Kernel 2: persistent-B fp16 MMA, ldmatrix, 3-stage A pipeline,
//   SINGLE __syncthreads per iteration.  Grid (8,3,12) = 288 CTAs,
//   2 CTAs/SM.  (R14 verbatim)
// ---------------------------------------------------------------------------
#define T2    256
#define SA2   104                      // halfs per smem row (208B, conflict-free)
#define BS2H  (128 * SA2)              // 13312 halfs
#define AS2H  (128 * SA2)
#define SMEM2 ((BS2H + 3 * AS2H) * 2)  // 106496 B

__device__ __forceinline__ void k2_stageA(uint32_t base, int tokbase, int tid)
{
#pragma unroll
    for (int i = 0; i < 6; i++) {      // 128 rows x 12 cp16
        int idx = i * T2 + tid;
        int row = idx / 12, q = idx % 12;
        cpasync16(base + (uint32_t)(row * SA2 + q * 8) * 2,
                  &g_coefh[(size_t)(tokbase + row) * NCOL + q * 8]);
    }
}

__global__ __launch_bounds__(T2, 2) void k2_mma(float* __restrict__ out, int ntok)
{
    extern __shared__ __half smh[];
    const uint32_t sbase = smem_u32(smh);

    const int tid = threadIdx.x;
    const int lane = tid & 31, wid = tid >> 5;
    const int m0 = (wid >> 2) * 64;    // 2 m-warps x 64
    const int n0 = (wid & 3) * 32;     // 4 n-warps x 32
    const int dbase = blockIdx.x * 128;
    const int h     = blockIdx.y;
    const int s     = blockIdx.z;      // 0..11
    const int niter = (64 - s + 11) / 12;

    const int la_row = (lane & 7) + ((lane >> 3) & 1) * 8;
    const int la_col = (lane >> 4) * 8;
    const int lb_row = (lane & 7) + (lane >> 4) * 8;
    const int lb_col = ((lane >> 3) & 1) * 8;

    // stage B + A0 (group 0); A1 (group 1)
#pragma unroll
    for (int i = 0; i < 6; i++) {
        int idx = i * T2 + tid;
        int row = idx / 12, q = idx % 12;
        cpasync16(sbase + (uint32_t)(row * SA2 + q * 8) * 2,
                  &g_loth[((size_t)h * D_OUTD + dbase + row) * NCOL + q * 8]);
    }
    k2_stageA(sbase + BS2H * 2, s * 128, tid);
    asm volatile("cp.async.commit_group;" ::: "memory");
    if (1 < niter) {
        k2_stageA(sbase + (BS2H + AS2H) * 2, (s + 12) * 128, tid);
        asm volatile("cp.async.commit_group;" ::: "memory");
    }

    for (int it = 0; it < niter; it++) {
        if (it + 1 < niter) {
            asm volatile("cp.async.wait_group 1;" ::: "memory");
        } else {
            asm volatile("cp.async.wait_group 0;" ::: "memory");
        }
        __syncthreads();
        if (it + 2 < niter) {
            k2_stageA(sbase + (BS2H + ((it + 2) % 3) * AS2H) * 2,
                      (s + 12 * (it + 2)) * 128, tid);
            asm volatile("cp.async.commit_group;" ::: "memory");
        }

        const uint32_t Ab = sbase + (uint32_t)(BS2H + (it % 3) * AS2H) * 2;

        float acc[4][4][4];
#pragma unroll
        for (int tm = 0; tm < 4; tm++)
#pragma unroll
            for (int tn = 0; tn < 4; tn++)
#pragma unroll
                for (int q = 0; q < 4; q++) acc[tm][tn][q] = 0.f;

#pragma unroll
        for (int ks = 0; ks < 6; ks++) {
            const int k0h = ks * 16;
            uint32_t a[4][4], b[4][2];
#pragma unroll
            for (int tm = 0; tm < 4; tm++) {
                uint32_t ad = Ab + (uint32_t)((m0 + tm * 16 + la_row) * SA2 + k0h + la_col) * 2;
                LDMX4(a[tm][0], a[tm][1], a[tm][2], a[tm][3], ad);
            }
#pragma unroll
            for (int tp = 0; tp < 2; tp++) {
                uint32_t bd = sbase + (uint32_t)((n0 + tp * 16 + lb_row) * SA2 + k0h + lb_col) * 2;
                LDMX4(b[2 * tp][0], b[2 * tp][1], b[2 * tp + 1][0], b[2 * tp + 1][1], bd);
            }
#pragma unroll
            for (int tm = 0; tm < 4; tm++)
#pragma unroll
                for (int tn = 0; tn < 4; tn++)
                    MMA_F16(acc[tm][tn], a[tm], b[tn]);
        }

        // epilogue
        const int tokbase = (s + 12 * it) * 128;
#pragma unroll
        for (int tm = 0; tm < 4; tm++) {
            const size_t row0 = (size_t)tokbase + m0 + tm * 16 + (lane >> 2);
            float* ob = out + ((size_t)h * ntok + row0) * D_OUTD + dbase + n0 + 2 * (lane & 3);
#pragma unroll
            for (int tn = 0; tn < 4; tn++) {
                float2 v0; v0.x = acc[tm][tn][0]; v0.y = acc[tm][tn][1];
                float2 v1; v1.x = acc[tm][tn][2]; v1.y = acc[tm][tn][3];
                *(float2*)(ob + tn * 8) = v0;
                *(float2*)(ob + tn * 8 + 8 * D_OUTD) = v1;
            }
        }
    }
}

// ---------------------------------------------------------------------------
extern "C" void kernel_launch(void* const* d_in, const int* in_sizes, int n_in,
                              void* d_out, int out_size)
{
    const float* x   = (const float*)d_in[0];
    const float* dw  = (const float*)d_in[1];
    const float* db  = (const float*)d_in[2];
    const float* ntl = (const float*)d_in[3];
    const float* lo  = (const float*)d_in[4];
    const float* gw  = (const float*)d_in[5];
    const float* gb  = (const float*)d_in[6];
    float* out = (float*)d_out;

    int ntok = in_sizes[0] / D_IN;   // 8192

    cudaFuncSetAttribute(k1_mma, cudaFuncAttributeMaxDynamicSharedMemorySize, SMEM1);
    cudaFuncSetAttribute(k2_mma, cudaFuncAttributeMaxDynamicSharedMemorySize, SMEM2);

    k_prep<<<NCOL + 288, 256>>>(dw, gw, lo);
    k1_mma<<<ntok / 32, T1, SMEM1>>>(x, db, ntl, gb, ntok);

    dim3 g2(D_OUTD / 128, NHEADS, 12);
    k2_mma<<<g2, T2, SMEM2>>>(out, ntok);
}